// round 1
// baseline (speedup 1.0000x reference)
#include <cuda_runtime.h>

// Problem constants
#define BATCH 32
#define HDIM  56
#define WDIM  56
#define CIN   256
#define COUT  256
#define MTOT  (BATCH*HDIM*WDIM)   // 100352
#define KTOT  (3*3*CIN)           // 2304

// Tiling
#define BM 128
#define BN 128
#define BK 16
#define NKT (KTOT/BK)             // 144

__global__ __launch_bounds__(256) void conv3x3_f32x2_kernel(
    const float* __restrict__ in,    // [B,H,W,CIN]
    const float* __restrict__ wt,    // [3,3,CIN,COUT]
    const float* __restrict__ bias,  // [COUT]
    float* __restrict__ out)         // [B,H,W,COUT]
{
    __shared__ float As[2][BK][BM];
    __shared__ float Bs[2][BK][BN];

    const int t  = threadIdx.x;
    const int bm = blockIdx.y * BM;
    const int bn = blockIdx.x * BN;

    // ---- A (input) loader mapping: each thread owns one M-row, 8 consecutive k ----
    const int la_m  = t >> 1;          // 0..127
    const int la_k4 = (t & 1) * 2;     // float4 column base (0 or 2) -> k 0..7 / 8..15
    const int gm    = bm + la_m;
    const int prem  = gm % (HDIM * WDIM);
    const int py    = prem / WDIM;
    const int px    = prem % WDIM;
    const float* in_pix = in + (size_t)gm * CIN;   // base pointer at (b,py,px,0)

    // ---- B (weight) loader mapping ----
    const int lb_k  = t >> 4;          // 0..15
    const int lb_n  = (t & 15) * 8;    // 8 floats per thread along n

    // ---- compute-thread mapping: 8 warps as 4(M) x 2(N); 8x8 outputs/thread ----
    const int warp = t >> 5, lane = t & 31;
    const int wm = warp & 3, wn = warp >> 2;
    const int tm0 = wm * 32 + (lane >> 3) * 4;   // rows tm0..tm0+3, tm0+16..tm0+19
    const int tn0 = wn * 64 + (lane & 7) * 4;    // cols tn0..tn0+3, tn0+32..tn0+35

    unsigned long long acc[8][4];
    #pragma unroll
    for (int i = 0; i < 8; i++)
        #pragma unroll
        for (int j = 0; j < 4; j++) acc[i][j] = 0ull;

    float4 ra[2], rb[2];

    auto loadA = [&](int kt, float4* r) {
        const int k0  = kt * BK;
        const int ky  = k0 / (3 * CIN);
        const int rem = k0 % (3 * CIN);
        const int kx  = rem / CIN;
        const int ci0 = rem % CIN;
        const int iy  = py + ky - 1;
        const int ix  = px + kx - 1;
        const bool ok = ((unsigned)iy < HDIM) && ((unsigned)ix < WDIM);
        const float* p = in_pix + ((ky - 1) * WDIM + (kx - 1)) * CIN + ci0 + la_k4 * 4;
        if (ok) {
            r[0] = *(const float4*)(p);
            r[1] = *(const float4*)(p + 4);
        } else {
            r[0] = make_float4(0.f, 0.f, 0.f, 0.f);
            r[1] = make_float4(0.f, 0.f, 0.f, 0.f);
        }
    };
    auto loadB = [&](int kt, float4* r) {
        const float* p = wt + (size_t)(kt * BK + lb_k) * COUT + bn + lb_n;
        r[0] = *(const float4*)(p);
        r[1] = *(const float4*)(p + 4);
    };
    auto storeA = [&](int buf, const float4* r) {
        #pragma unroll
        for (int j = 0; j < 2; j++) {
            const int kk = (la_k4 + j) * 4;
            As[buf][kk + 0][la_m] = r[j].x;
            As[buf][kk + 1][la_m] = r[j].y;
            As[buf][kk + 2][la_m] = r[j].z;
            As[buf][kk + 3][la_m] = r[j].w;
        }
    };
    auto storeB = [&](int buf, const float4* r) {
        *(float4*)&Bs[buf][lb_k][lb_n]     = r[0];
        *(float4*)&Bs[buf][lb_k][lb_n + 4] = r[1];
    };

    // prologue: fill buffer 0
    loadA(0, ra); loadB(0, rb);
    storeA(0, ra); storeB(0, rb);
    __syncthreads();

    #pragma unroll 1
    for (int kt = 0; kt < NKT; kt++) {
        const int buf = kt & 1;
        if (kt + 1 < NKT) { loadA(kt + 1, ra); loadB(kt + 1, rb); }

        #pragma unroll
        for (int kk = 0; kk < BK; kk++) {
            const float4 a0 = *(const float4*)&As[buf][kk][tm0];
            const float4 a1 = *(const float4*)&As[buf][kk][tm0 + 16];
            const unsigned long long* bp0 = (const unsigned long long*)&Bs[buf][kk][tn0];
            const unsigned long long* bp1 = (const unsigned long long*)&Bs[buf][kk][tn0 + 32];
            const unsigned long long b0 = bp0[0], b1 = bp0[1];
            const unsigned long long b2 = bp1[0], b3 = bp1[1];
            const float av[8] = {a0.x, a0.y, a0.z, a0.w, a1.x, a1.y, a1.z, a1.w};
            #pragma unroll
            for (int i = 0; i < 8; i++) {
                unsigned long long pa;
                asm("mov.b64 %0, {%1, %1};" : "=l"(pa) : "f"(av[i]));
                asm("fma.rn.f32x2 %0, %1, %2, %0;" : "+l"(acc[i][0]) : "l"(pa), "l"(b0));
                asm("fma.rn.f32x2 %0, %1, %2, %0;" : "+l"(acc[i][1]) : "l"(pa), "l"(b1));
                asm("fma.rn.f32x2 %0, %1, %2, %0;" : "+l"(acc[i][2]) : "l"(pa), "l"(b2));
                asm("fma.rn.f32x2 %0, %1, %2, %0;" : "+l"(acc[i][3]) : "l"(pa), "l"(b3));
            }
        }

        if (kt + 1 < NKT) {
            // writes go to buf^1; all readers of buf^1 finished before the
            // barrier that ended iteration kt-1, so one sync suffices.
            storeA(buf ^ 1, ra); storeB(buf ^ 1, rb);
            __syncthreads();
        }
    }

    // ---- epilogue: unpack, add bias, store ----
    const float4 blo = *(const float4*)(bias + bn + tn0);
    const float4 bhi = *(const float4*)(bias + bn + tn0 + 32);

    #pragma unroll
    for (int i = 0; i < 8; i++) {
        const int m = bm + tm0 + ((i < 4) ? i : (12 + i));  // tm0+0..3, tm0+16..19
        float* po = out + (size_t)m * COUT + bn + tn0;
        float v0, v1, v2, v3, v4, v5, v6, v7;
        asm("mov.b64 {%0,%1}, %2;" : "=f"(v0), "=f"(v1) : "l"(acc[i][0]));
        asm("mov.b64 {%0,%1}, %2;" : "=f"(v2), "=f"(v3) : "l"(acc[i][1]));
        asm("mov.b64 {%0,%1}, %2;" : "=f"(v4), "=f"(v5) : "l"(acc[i][2]));
        asm("mov.b64 {%0,%1}, %2;" : "=f"(v6), "=f"(v7) : "l"(acc[i][3]));
        const float4 o0 = make_float4(v0 + blo.x, v1 + blo.y, v2 + blo.z, v3 + blo.w);
        const float4 o1 = make_float4(v4 + bhi.x, v5 + bhi.y, v6 + bhi.z, v7 + bhi.w);
        *(float4*)(po)      = o0;
        *(float4*)(po + 32) = o1;
    }
}

extern "C" void kernel_launch(void* const* d_in, const int* in_sizes, int n_in,
                              void* d_out, int out_size) {
    const float* in   = (const float*)d_in[0];   // inputs [32,56,56,256] f32
    const float* wt   = (const float*)d_in[1];   // kernel [3,3,256,256]  f32 (HWIO)
    const float* bias = (const float*)d_in[2];   // bias   [256]          f32
    float* out = (float*)d_out;                  // [32,56,56,256] f32

    dim3 grid(COUT / BN, MTOT / BM);  // (2, 784)
    conv3x3_f32x2_kernel<<<grid, 256>>>(in, wt, bias, out);
}

// round 4
// speedup vs baseline: 1.3677x; 1.3677x over previous
#include <cuda_runtime.h>
#include <cuda_bf16.h>
#include <cstdint>

#define BATCH 32
#define HDIM  56
#define WDIM  56
#define CIN   256
#define COUT  256
#define HP    58
#define WP    58
#define MTOT  (BATCH*HDIM*WDIM)        // 100352
#define NPIX_PAD (BATCH*HP*WP)         // 107648
#define NCHUNK 72                      // 9 taps * 8 chunks of 32 channels

// scratch: padded activations [pix][8 chunks][hi 32ch 64B | lo 32ch 64B]
__device__ __align__(1024) unsigned char g_apad[(size_t)NPIX_PAD * 1024];
// packed weights: [tap 9][chunk 8][co 256][hi 32 | lo 32] -> 128B rows
__device__ __align__(1024) unsigned char g_bpack[9*8*256*128];

// ---------------- prep kernels ----------------
// 2 pixels per block: threads 0-63 -> pixel 2*bid, threads 64-127 -> pixel 2*bid+1.
// Each thread handles exactly 4 of the 256 channels (64*4 = 256).
__global__ void prep_a_kernel(const float* __restrict__ in) {
    const int t   = threadIdx.x;
    const int pix = blockIdx.x * 2 + (t >> 6);
    const int tt  = t & 63;
    const int b   = pix / (HP*WP);
    const int rr  = pix % (HP*WP);
    const int yp  = rr / WP, xp = rr % WP;
    const int c0  = tt * 4;               // 0..252
    const int g   = c0 >> 5, i = c0 & 31;
    unsigned long long hw = 0ull, lw = 0ull;
    if (!(yp == 0 || yp == HP-1 || xp == 0 || xp == WP-1)) {
        const float4 v = *(const float4*)(in +
            ((size_t)((b*HDIM + (yp-1))*WDIM + (xp-1)))*CIN + c0);
        const float vv[4] = {v.x, v.y, v.z, v.w};
        #pragma unroll
        for (int j = 0; j < 4; j++) {
            __nv_bfloat16 h = __float2bfloat16(vv[j]);
            __nv_bfloat16 l = __float2bfloat16(vv[j] - __bfloat162float(h));
            hw |= (unsigned long long)(*(unsigned short*)&h) << (16*j);
            lw |= (unsigned long long)(*(unsigned short*)&l) << (16*j);
        }
    }
    unsigned char* base = g_apad + (size_t)pix*1024 + g*128 + i*2;
    *(unsigned long long*)(base)      = hw;
    *(unsigned long long*)(base + 64) = lw;
}

__global__ void prep_b_kernel(const float* __restrict__ wt) {
    const int k  = blockIdx.x;       // 0..2303 : (ky*3+kx)*256 + ci
    const int co = threadIdx.x;      // 0..255
    const float v = wt[(size_t)k*COUT + co];
    __nv_bfloat16 h = __float2bfloat16(v);
    __nv_bfloat16 l = __float2bfloat16(v - __bfloat162float(h));
    const int tap = k >> 8, ci = k & 255;
    const int chunk = ci >> 5, i = ci & 31;
    unsigned char* base = g_bpack + ((size_t)((tap*8 + chunk)*256 + co))*128 + i*2;
    *(unsigned short*)(base)      = *(unsigned short*)&h;
    *(unsigned short*)(base + 64) = *(unsigned short*)&l;
}

// ---------------- device helpers ----------------
__device__ __forceinline__ uint32_t smem_u32(const void* p) {
    uint32_t a;
    asm("{ .reg .u64 t; cvta.to.shared.u64 t, %1; cvt.u32.u64 %0, t; }" : "=r"(a) : "l"(p));
    return a;
}

#define LDSM4(r0,r1,r2,r3,addr) \
    asm volatile("ldmatrix.sync.aligned.m8n8.x4.shared.b16 {%0,%1,%2,%3}, [%4];" \
        : "=r"(r0), "=r"(r1), "=r"(r2), "=r"(r3) : "r"(addr))

__device__ __forceinline__ void mma16816(float* c, const uint32_t* a, const uint32_t* b) {
    asm volatile(
        "mma.sync.aligned.m16n8k16.row.col.f32.bf16.bf16.f32 "
        "{%0,%1,%2,%3}, {%4,%5,%6,%7}, {%8,%9}, {%0,%1,%2,%3};"
        : "+f"(c[0]), "+f"(c[1]), "+f"(c[2]), "+f"(c[3])
        : "r"(a[0]), "r"(a[1]), "r"(a[2]), "r"(a[3]), "r"(b[0]), "r"(b[1]));
}

// ---------------- main conv kernel ----------------
__global__ void __launch_bounds__(256) conv_mma_kernel(
    const float* __restrict__ bias, float* __restrict__ out)
{
    extern __shared__ unsigned char smem[];
    const uint32_t sb = smem_u32(smem);
    const int t = threadIdx.x;
    const int lane = t & 31, warp = t >> 5;
    const int bm = blockIdx.y * 128;
    const int bn = blockIdx.x * 128;
    const int m0 = (warp >> 2) * 64;     // 2 m-warps
    const int n0 = (warp & 3) * 32;      // 4 n-warps

    // ---- loader setup: t<128 -> A row t; t>=128 -> B row t-128 ----
    const unsigned char* gA = nullptr;
    const unsigned char* gB = nullptr;
    if (t < 128) {
        const int m  = bm + t;
        const int b  = m / (HDIM*WDIM);
        const int r2 = m % (HDIM*WDIM);
        const int y  = r2 / WDIM, x = r2 % WDIM;
        gA = g_apad + (size_t)((b*HP + y)*WP + x) * 1024;
    } else {
        gB = g_bpack + ((size_t)(bn + (t - 128))) * 128;
    }
    const int lrow = t & 127;
    const uint32_t swz = (uint32_t)((lrow & 7) << 4);
    const uint32_t sdst_row = (t < 128) ? (uint32_t)(lrow * 128)
                                        : (uint32_t)(16384 + lrow * 128);

    auto load_chunk = [&](int c, int buf) {
        const unsigned char* src;
        if (t < 128) {
            const int tap = c >> 3;
            src = gA + (size_t)((tap/3)*WP + (tap%3))*1024 + (c & 7)*128;
        } else {
            src = gB + (size_t)c * (256*128);
        }
        const uint32_t dst = sb + buf*32768 + sdst_row;
        #pragma unroll
        for (int j = 0; j < 8; j++) {
            const uint32_t o = ((uint32_t)(j*16)) ^ swz;
            asm volatile("cp.async.cg.shared.global [%0], [%1], 16;"
                         :: "r"(dst + o), "l"(src + j*16) : "memory");
        }
        asm volatile("cp.async.commit_group;" ::: "memory");
    };

    // ---- ldmatrix lane addressing ----
    const uint32_t lr   = (uint32_t)(lane & 15);
    const uint32_t koff = (uint32_t)((lane >> 4) << 4);
    const uint32_t xorv = (uint32_t)((lane & 7) << 4);

    float acc[4][4][4];
    #pragma unroll
    for (int i = 0; i < 4; i++)
        #pragma unroll
        for (int j = 0; j < 4; j++)
            #pragma unroll
            for (int k = 0; k < 4; k++) acc[i][j][k] = 0.f;

    load_chunk(0, 0);

    #pragma unroll 1
    for (int c = 0; c < NCHUNK; c++) {
        const int buf = c & 1;
        if (c + 1 < NCHUNK) {
            load_chunk(c + 1, buf ^ 1);
            asm volatile("cp.async.wait_group 1;" ::: "memory");
        } else {
            asm volatile("cp.async.wait_group 0;" ::: "memory");
        }
        __syncthreads();

        const uint32_t Ab = sb + buf*32768;
        const uint32_t Bb = Ab + 16384;

        #pragma unroll
        for (int kh = 0; kh < 2; kh++) {
            uint32_t ah[4][4], al[4][4], bh[4][2], bl[4][2];
            const uint32_t chi = (uint32_t)(kh*32) + koff;
            const uint32_t clo = chi + 64;
            #pragma unroll
            for (int mi = 0; mi < 4; mi++) {
                const uint32_t r = Ab + (uint32_t)(m0 + mi*16 + lr)*128;
                LDSM4(ah[mi][0], ah[mi][1], ah[mi][2], ah[mi][3], r + (chi ^ xorv));
                LDSM4(al[mi][0], al[mi][1], al[mi][2], al[mi][3], r + (clo ^ xorv));
            }
            #pragma unroll
            for (int nb = 0; nb < 2; nb++) {
                const uint32_t r = Bb + (uint32_t)(n0 + nb*16 + lr)*128;
                uint32_t b0, b1, b2, b3;
                LDSM4(b0, b1, b2, b3, r + (chi ^ xorv));
                bh[nb*2][0] = b0; bh[nb*2][1] = b2;
                bh[nb*2+1][0] = b1; bh[nb*2+1][1] = b3;
                LDSM4(b0, b1, b2, b3, r + (clo ^ xorv));
                bl[nb*2][0] = b0; bl[nb*2][1] = b2;
                bl[nb*2+1][0] = b1; bl[nb*2+1][1] = b3;
            }
            // pass 1: Ah*Bh
            #pragma unroll
            for (int mi = 0; mi < 4; mi++)
                #pragma unroll
                for (int ni = 0; ni < 4; ni++)
                    mma16816(acc[mi][ni], ah[mi], bh[ni]);
            // pass 2: Al*Bh
            #pragma unroll
            for (int mi = 0; mi < 4; mi++)
                #pragma unroll
                for (int ni = 0; ni < 4; ni++)
                    mma16816(acc[mi][ni], al[mi], bh[ni]);
            // pass 3: Ah*Bl
            #pragma unroll
            for (int mi = 0; mi < 4; mi++)
                #pragma unroll
                for (int ni = 0; ni < 4; ni++)
                    mma16816(acc[mi][ni], ah[mi], bl[ni]);
        }
        __syncthreads();
    }

    // ---- epilogue ----
    const int g = lane >> 2, q = lane & 3;
    #pragma unroll
    for (int ni = 0; ni < 4; ni++) {
        const int ncol = bn + n0 + ni*8 + q*2;
        const float2 bv = *(const float2*)(bias + ncol);
        #pragma unroll
        for (int mi = 0; mi < 4; mi++) {
            const int mrow = bm + m0 + mi*16 + g;
            float2 o0, o1;
            o0.x = acc[mi][ni][0] + bv.x; o0.y = acc[mi][ni][1] + bv.y;
            o1.x = acc[mi][ni][2] + bv.x; o1.y = acc[mi][ni][3] + bv.y;
            *(float2*)(out + (size_t)mrow*COUT + ncol)       = o0;
            *(float2*)(out + (size_t)(mrow+8)*COUT + ncol)   = o1;
        }
    }
}

// ---------------- launch ----------------
extern "C" void kernel_launch(void* const* d_in, const int* in_sizes, int n_in,
                              void* d_out, int out_size) {
    const float* in   = (const float*)d_in[0];   // [32,56,56,256] f32
    const float* wt   = (const float*)d_in[1];   // [3,3,256,256]  f32
    const float* bias = (const float*)d_in[2];   // [256]          f32
    float* out = (float*)d_out;

    static int smem_set = 0;
    if (!smem_set) {
        cudaFuncSetAttribute(conv_mma_kernel,
                             cudaFuncAttributeMaxDynamicSharedMemorySize, 65536);
        smem_set = 1;
    }

    prep_a_kernel<<<NPIX_PAD/2, 128>>>(in);
    prep_b_kernel<<<9*256, 256>>>(wt);
    dim3 grid(2, MTOT/128);   // (2, 784)
    conv_mma_kernel<<<grid, 256, 65536>>>(bias, out);
}

// round 5
// speedup vs baseline: 1.9661x; 1.4375x over previous
#include <cuda_runtime.h>
#include <cuda_fp16.h>
#include <cstdint>

#define BATCH 32
#define HDIM  56
#define WDIM  56
#define CIN   256
#define COUT  256
#define HP    58
#define WP    58
#define MTOT  (BATCH*HDIM*WDIM)        // 100352
#define NPIX_PAD (BATCH*HP*WP)         // 107648
#define NCHUNK 36                      // 9 taps * 4 chunks of 64 channels

#define STAGE_BYTES 49152              // A 16KB | Bh 16KB | Bl 16KB

// padded activations, fp16: [pix][4 chunks][64ch * 2B] = 512B/pixel
__device__ __align__(1024) unsigned char g_apad[(size_t)NPIX_PAD * 512];
// packed weights fp16 hi/lo: [tap 9][chunk 4][co 256][hi 128B | lo 128B]
__device__ __align__(1024) unsigned char g_bpack[9*4*256*256];

// ---------------- prep kernels ----------------
// 2 pixels per 128-thread block; 64 threads x 4 channels = 256 channels each.
__global__ void prep_a_kernel(const float* __restrict__ in) {
    const int t   = threadIdx.x;
    const int pix = blockIdx.x * 2 + (t >> 6);
    const int tt  = t & 63;
    const int b   = pix / (HP*WP);
    const int rr  = pix % (HP*WP);
    const int yp  = rr / WP, xp = rr % WP;
    const int c0  = tt * 4;               // 0..252
    const int chunk = c0 >> 6, i = c0 & 63;
    unsigned long long hw = 0ull;
    if (!(yp == 0 || yp == HP-1 || xp == 0 || xp == WP-1)) {
        const float4 v = *(const float4*)(in +
            ((size_t)((b*HDIM + (yp-1))*WDIM + (xp-1)))*CIN + c0);
        const float vv[4] = {v.x, v.y, v.z, v.w};
        #pragma unroll
        for (int j = 0; j < 4; j++) {
            __half h = __float2half_rn(vv[j]);
            hw |= (unsigned long long)(*(unsigned short*)&h) << (16*j);
        }
    }
    *(unsigned long long*)(g_apad + (size_t)pix*512 + chunk*128 + i*2) = hw;
}

__global__ void prep_b_kernel(const float* __restrict__ wt) {
    const int k  = blockIdx.x;       // 0..2303 : (ky*3+kx)*256 + ci
    const int co = threadIdx.x;      // 0..255
    const float v = wt[(size_t)k*COUT + co];
    __half h = __float2half_rn(v);
    __half l = __float2half_rn(v - __half2float(h));
    const int tap = k >> 8, ci = k & 255;
    const int chunk = ci >> 6, i = ci & 63;
    unsigned char* base = g_bpack + ((size_t)((tap*4 + chunk)*256 + co))*256 + i*2;
    *(unsigned short*)(base)       = *(unsigned short*)&h;
    *(unsigned short*)(base + 128) = *(unsigned short*)&l;
}

// ---------------- device helpers ----------------
__device__ __forceinline__ uint32_t smem_u32(const void* p) {
    uint32_t a;
    asm("{ .reg .u64 t; cvta.to.shared.u64 t, %1; cvt.u32.u64 %0, t; }" : "=r"(a) : "l"(p));
    return a;
}

#define LDSM4(r0,r1,r2,r3,addr) \
    asm volatile("ldmatrix.sync.aligned.m8n8.x4.shared.b16 {%0,%1,%2,%3}, [%4];" \
        : "=r"(r0), "=r"(r1), "=r"(r2), "=r"(r3) : "r"(addr))

__device__ __forceinline__ void mma16816(float* c, const uint32_t* a, const uint32_t* b) {
    asm volatile(
        "mma.sync.aligned.m16n8k16.row.col.f32.f16.f16.f32 "
        "{%0,%1,%2,%3}, {%4,%5,%6,%7}, {%8,%9}, {%0,%1,%2,%3};"
        : "+f"(c[0]), "+f"(c[1]), "+f"(c[2]), "+f"(c[3])
        : "r"(a[0]), "r"(a[1]), "r"(a[2]), "r"(a[3]), "r"(b[0]), "r"(b[1]));
}

// ---------------- main conv kernel ----------------
__global__ void __launch_bounds__(256) conv_mma_kernel(
    const float* __restrict__ bias, float* __restrict__ out)
{
    extern __shared__ unsigned char smem[];
    const uint32_t sb = smem_u32(smem);
    const int t = threadIdx.x;
    const int lane = t & 31, warp = t >> 5;
    const int bm = blockIdx.y * 128;
    const int bn = blockIdx.x * 128;
    const int m0 = (warp >> 2) * 64;     // 2 m-warps
    const int n0 = (warp & 3) * 32;      // 4 n-warps

    // ---- loader setup: t<128 -> A row t; t>=128 -> B row t-128 ----
    const unsigned char* gA = nullptr;
    const unsigned char* gB = nullptr;
    if (t < 128) {
        const int m  = bm + t;
        const int b  = m / (HDIM*WDIM);
        const int r2 = m % (HDIM*WDIM);
        const int y  = r2 / WDIM, x = r2 % WDIM;
        gA = g_apad + (size_t)((b*HP + y)*WP + x) * 512;
    } else {
        gB = g_bpack + ((size_t)(bn + (t - 128))) * 256;
    }
    const int lrow = t & 127;
    const uint32_t swz = (uint32_t)((lrow & 7) << 4);

    auto load_chunk = [&](int c, int buf) {
        if (t < 128) {
            const int tap = c >> 2;
            const unsigned char* src = gA + (size_t)((tap/3)*WP + (tap%3))*512 + (c & 3)*128;
            const uint32_t dst = sb + buf*STAGE_BYTES + lrow*128;
            #pragma unroll
            for (int j = 0; j < 8; j++) {
                const uint32_t o = ((uint32_t)(j*16)) ^ swz;
                asm volatile("cp.async.cg.shared.global [%0], [%1], 16;"
                             :: "r"(dst + o), "l"(src + j*16) : "memory");
            }
        } else {
            const unsigned char* src = gB + (size_t)c * (256*256);
            const uint32_t dsth = sb + buf*STAGE_BYTES + 16384 + lrow*128;
            const uint32_t dstl = dsth + 16384;
            #pragma unroll
            for (int j = 0; j < 8; j++) {
                const uint32_t o = ((uint32_t)(j*16)) ^ swz;
                asm volatile("cp.async.cg.shared.global [%0], [%1], 16;"
                             :: "r"(dsth + o), "l"(src + j*16) : "memory");
                asm volatile("cp.async.cg.shared.global [%0], [%1], 16;"
                             :: "r"(dstl + o), "l"(src + 128 + j*16) : "memory");
            }
        }
        asm volatile("cp.async.commit_group;" ::: "memory");
    };

    // ---- ldmatrix lane addressing ----
    const uint32_t lr   = (uint32_t)(lane & 15);
    const uint32_t koff = (uint32_t)((lane >> 4) << 4);
    const uint32_t xorv = (uint32_t)((lane & 7) << 4);

    float acc[4][4][4];
    #pragma unroll
    for (int i = 0; i < 4; i++)
        #pragma unroll
        for (int j = 0; j < 4; j++)
            #pragma unroll
            for (int k = 0; k < 4; k++) acc[i][j][k] = 0.f;

    load_chunk(0, 0);

    #pragma unroll 1
    for (int c = 0; c < NCHUNK; c++) {
        const int buf = c & 1;
        if (c + 1 < NCHUNK) {
            load_chunk(c + 1, buf ^ 1);
            asm volatile("cp.async.wait_group 1;" ::: "memory");
        } else {
            asm volatile("cp.async.wait_group 0;" ::: "memory");
        }
        __syncthreads();

        const uint32_t Ab = sb + buf*STAGE_BYTES;
        const uint32_t Bh = Ab + 16384;
        const uint32_t Bl = Ab + 32768;

        #pragma unroll
        for (int kh = 0; kh < 4; kh++) {
            uint32_t ah[4][4], bh[4][2], bl[4][2];
            const uint32_t chi = (uint32_t)(kh*32) + koff;
            #pragma unroll
            for (int mi = 0; mi < 4; mi++) {
                const uint32_t r = Ab + (uint32_t)(m0 + mi*16 + lr)*128;
                LDSM4(ah[mi][0], ah[mi][1], ah[mi][2], ah[mi][3], r + (chi ^ xorv));
            }
            #pragma unroll
            for (int nb = 0; nb < 2; nb++) {
                const uint32_t rh = Bh + (uint32_t)(n0 + nb*16 + lr)*128;
                const uint32_t rl = Bl + (uint32_t)(n0 + nb*16 + lr)*128;
                uint32_t b0, b1, b2, b3;
                LDSM4(b0, b1, b2, b3, rh + (chi ^ xorv));
                bh[nb*2][0] = b0; bh[nb*2][1] = b2;
                bh[nb*2+1][0] = b1; bh[nb*2+1][1] = b3;
                LDSM4(b0, b1, b2, b3, rl + (chi ^ xorv));
                bl[nb*2][0] = b0; bl[nb*2][1] = b2;
                bl[nb*2+1][0] = b1; bl[nb*2+1][1] = b3;
            }
            // pass 1: A*Bh
            #pragma unroll
            for (int mi = 0; mi < 4; mi++)
                #pragma unroll
                for (int ni = 0; ni < 4; ni++)
                    mma16816(acc[mi][ni], ah[mi], bh[ni]);
            // pass 2: A*Bl
            #pragma unroll
            for (int mi = 0; mi < 4; mi++)
                #pragma unroll
                for (int ni = 0; ni < 4; ni++)
                    mma16816(acc[mi][ni], ah[mi], bl[ni]);
        }
        __syncthreads();
    }

    // ---- epilogue ----
    const int g = lane >> 2, q = lane & 3;
    #pragma unroll
    for (int ni = 0; ni < 4; ni++) {
        const int ncol = bn + n0 + ni*8 + q*2;
        const float2 bv = *(const float2*)(bias + ncol);
        #pragma unroll
        for (int mi = 0; mi < 4; mi++) {
            const int mrow = bm + m0 + mi*16 + g;
            float2 o0, o1;
            o0.x = acc[mi][ni][0] + bv.x; o0.y = acc[mi][ni][1] + bv.y;
            o1.x = acc[mi][ni][2] + bv.x; o1.y = acc[mi][ni][3] + bv.y;
            *(float2*)(out + (size_t)mrow*COUT + ncol)       = o0;
            *(float2*)(out + (size_t)(mrow+8)*COUT + ncol)   = o1;
        }
    }
}

// ---------------- launch ----------------
extern "C" void kernel_launch(void* const* d_in, const int* in_sizes, int n_in,
                              void* d_out, int out_size) {
    const float* in   = (const float*)d_in[0];   // [32,56,56,256] f32
    const float* wt   = (const float*)d_in[1];   // [3,3,256,256]  f32
    const float* bias = (const float*)d_in[2];   // [256]          f32
    float* out = (float*)d_out;

    static int smem_set = 0;
    if (!smem_set) {
        cudaFuncSetAttribute(conv_mma_kernel,
                             cudaFuncAttributeMaxDynamicSharedMemorySize, 2*STAGE_BYTES);
        smem_set = 1;
    }

    prep_a_kernel<<<NPIX_PAD/2, 128>>>(in);
    prep_b_kernel<<<9*256, 256>>>(wt);
    dim3 grid(2, MTOT/128);   // (2, 784)
    conv_mma_kernel<<<grid, 256, 2*STAGE_BYTES>>>(bias, out);
}

// round 7
// speedup vs baseline: 3.2079x; 1.6316x over previous
#include <cuda_runtime.h>
#include <cuda_fp16.h>
#include <cstdint>

#define BATCH 32
#define HDIM  56
#define WDIM  56
#define CIN   256
#define COUT  256
#define HP    58
#define WP    58
#define MTOT  (BATCH*HDIM*WDIM)        // 100352
#define NPIX_PAD (BATCH*HP*WP)         // 107648
#define NCHUNK 36                      // 9 taps * 4 chunks of 64 channels

#define STAGE_BYTES 32768              // A 16KB | B 16KB

// padded activations, fp16: [pix][4 chunks][64ch * 2B] = 512B/pixel
__device__ __align__(1024) unsigned char g_apad[(size_t)NPIX_PAD * 512];
// packed weights fp16: [tap 9][chunk 4][co 256][64ch * 2B = 128B]
__device__ __align__(1024) unsigned char g_bpack[9*4*256*128];

// ---------------- prep kernels ----------------
// 2 pixels per 128-thread block; 64 threads x 4 channels = 256 channels each.
__global__ void prep_a_kernel(const float* __restrict__ in) {
    const int t   = threadIdx.x;
    const int pix = blockIdx.x * 2 + (t >> 6);
    const int tt  = t & 63;
    const int b   = pix / (HP*WP);
    const int rr  = pix % (HP*WP);
    const int yp  = rr / WP, xp = rr % WP;
    const int c0  = tt * 4;               // 0..252
    const int chunk = c0 >> 6, i = c0 & 63;
    unsigned long long hw = 0ull;
    if (!(yp == 0 || yp == HP-1 || xp == 0 || xp == WP-1)) {
        const float4 v = *(const float4*)(in +
            ((size_t)((b*HDIM + (yp-1))*WDIM + (xp-1)))*CIN + c0);
        const float vv[4] = {v.x, v.y, v.z, v.w};
        #pragma unroll
        for (int j = 0; j < 4; j++) {
            __half h = __float2half_rn(vv[j]);
            hw |= (unsigned long long)(*(unsigned short*)&h) << (16*j);
        }
    }
    *(unsigned long long*)(g_apad + (size_t)pix*512 + chunk*128 + i*2) = hw;
}

__global__ void prep_b_kernel(const float* __restrict__ wt) {
    const int k  = blockIdx.x;       // 0..2303 : (ky*3+kx)*256 + ci
    const int co = threadIdx.x;      // 0..255
    const float v = wt[(size_t)k*COUT + co];
    __half h = __float2half_rn(v);
    const int tap = k >> 8, ci = k & 255;
    const int chunk = ci >> 6, i = ci & 63;
    *(unsigned short*)(g_bpack + ((size_t)((tap*4 + chunk)*256 + co))*128 + i*2)
        = *(unsigned short*)&h;
}

// ---------------- device helpers ----------------
__device__ __forceinline__ uint32_t smem_u32(const void* p) {
    uint32_t a;
    asm("{ .reg .u64 t; cvta.to.shared.u64 t, %1; cvt.u32.u64 %0, t; }" : "=r"(a) : "l"(p));
    return a;
}

#define LDSM4(r0,r1,r2,r3,addr) \
    asm volatile("ldmatrix.sync.aligned.m8n8.x4.shared.b16 {%0,%1,%2,%3}, [%4];" \
        : "=r"(r0), "=r"(r1), "=r"(r2), "=r"(r3) : "r"(addr))

__device__ __forceinline__ void mma16816(float* c, const uint32_t* a, const uint32_t* b) {
    asm volatile(
        "mma.sync.aligned.m16n8k16.row.col.f32.f16.f16.f32 "
        "{%0,%1,%2,%3}, {%4,%5,%6,%7}, {%8,%9}, {%0,%1,%2,%3};"
        : "+f"(c[0]), "+f"(c[1]), "+f"(c[2]), "+f"(c[3])
        : "r"(a[0]), "r"(a[1]), "r"(a[2]), "r"(a[3]), "r"(b[0]), "r"(b[1]));
}

// ---------------- main conv kernel ----------------
__global__ void __launch_bounds__(256) conv_mma_kernel(
    const float* __restrict__ bias, float* __restrict__ out)
{
    extern __shared__ unsigned char smem[];
    const uint32_t sb = smem_u32(smem);
    const int t = threadIdx.x;
    const int lane = t & 31, warp = t >> 5;
    const int bm = blockIdx.y * 128;
    const int bn = blockIdx.x * 128;
    const int m0 = (warp >> 2) * 64;     // 2 m-warps
    const int n0 = (warp & 3) * 32;      // 4 n-warps

    // ---- loader setup: t<128 -> A row t; t>=128 -> B row t-128 ----
    const unsigned char* gA = nullptr;
    const unsigned char* gB = nullptr;
    if (t < 128) {
        const int m  = bm + t;
        const int b  = m / (HDIM*WDIM);
        const int r2 = m % (HDIM*WDIM);
        const int y  = r2 / WDIM, x = r2 % WDIM;
        gA = g_apad + (size_t)((b*HP + y)*WP + x) * 512;
    } else {
        gB = g_bpack + ((size_t)(bn + (t - 128))) * 128;
    }
    const int lrow = t & 127;
    const uint32_t swz = (uint32_t)((lrow & 7) << 4);
    const uint32_t sdst_row = (t < 128) ? (uint32_t)(lrow * 128)
                                        : (uint32_t)(16384 + lrow * 128);

    auto load_chunk = [&](int c, int buf) {
        const unsigned char* src;
        if (t < 128) {
            const int tap = c >> 2;
            src = gA + (size_t)((tap/3)*WP + (tap%3))*512 + (c & 3)*128;
        } else {
            src = gB + (size_t)c * (256*128);
        }
        const uint32_t dst = sb + buf*STAGE_BYTES + sdst_row;
        #pragma unroll
        for (int j = 0; j < 8; j++) {
            const uint32_t o = ((uint32_t)(j*16)) ^ swz;
            asm volatile("cp.async.cg.shared.global [%0], [%1], 16;"
                         :: "r"(dst + o), "l"(src + j*16) : "memory");
        }
        asm volatile("cp.async.commit_group;" ::: "memory");
    };

    // ---- ldmatrix lane addressing ----
    const uint32_t lr   = (uint32_t)(lane & 15);
    const uint32_t koff = (uint32_t)((lane >> 4) << 4);
    const uint32_t xorv = (uint32_t)((lane & 7) << 4);

    float acc[4][4][4];
    #pragma unroll
    for (int i = 0; i < 4; i++)
        #pragma unroll
        for (int j = 0; j < 4; j++)
            #pragma unroll
            for (int k = 0; k < 4; k++) acc[i][j][k] = 0.f;

    load_chunk(0, 0);

    #pragma unroll 1
    for (int c = 0; c < NCHUNK; c++) {
        const int buf = c & 1;
        if (c + 1 < NCHUNK) {
            load_chunk(c + 1, buf ^ 1);
            asm volatile("cp.async.wait_group 1;" ::: "memory");
        } else {
            asm volatile("cp.async.wait_group 0;" ::: "memory");
        }
        __syncthreads();

        const uint32_t Ab = sb + buf*STAGE_BYTES;
        const uint32_t Bb = Ab + 16384;

        #pragma unroll
        for (int kh = 0; kh < 4; kh++) {
            uint32_t ah[4][4], bh[4][2];
            const uint32_t chi = (uint32_t)(kh*32) + koff;
            #pragma unroll
            for (int mi = 0; mi < 4; mi++) {
                const uint32_t r = Ab + (uint32_t)(m0 + mi*16 + lr)*128;
                LDSM4(ah[mi][0], ah[mi][1], ah[mi][2], ah[mi][3], r + (chi ^ xorv));
            }
            #pragma unroll
            for (int nb = 0; nb < 2; nb++) {
                const uint32_t r = Bb + (uint32_t)(n0 + nb*16 + lr)*128;
                uint32_t b0, b1, b2, b3;
                LDSM4(b0, b1, b2, b3, r + (chi ^ xorv));
                bh[nb*2][0] = b0; bh[nb*2][1] = b2;
                bh[nb*2+1][0] = b1; bh[nb*2+1][1] = b3;
            }
            #pragma unroll
            for (int mi = 0; mi < 4; mi++)
                #pragma unroll
                for (int ni = 0; ni < 4; ni++)
                    mma16816(acc[mi][ni], ah[mi], bh[ni]);
        }
        __syncthreads();
    }

    // ---- epilogue ----
    const int g = lane >> 2, q = lane & 3;
    #pragma unroll
    for (int ni = 0; ni < 4; ni++) {
        const int ncol = bn + n0 + ni*8 + q*2;
        const float2 bv = *(const float2*)(bias + ncol);
        #pragma unroll
        for (int mi = 0; mi < 4; mi++) {
            const int mrow = bm + m0 + mi*16 + g;
            float2 o0, o1;
            o0.x = acc[mi][ni][0] + bv.x; o0.y = acc[mi][ni][1] + bv.y;
            o1.x = acc[mi][ni][2] + bv.x; o1.y = acc[mi][ni][3] + bv.y;
            *(float2*)(out + (size_t)mrow*COUT + ncol)       = o0;
            *(float2*)(out + (size_t)(mrow+8)*COUT + ncol)   = o1;
        }
    }
}

// ---------------- launch ----------------
extern "C" void kernel_launch(void* const* d_in, const int* in_sizes, int n_in,
                              void* d_out, int out_size) {
    const float* in   = (const float*)d_in[0];   // [32,56,56,256] f32
    const float* wt   = (const float*)d_in[1];   // [3,3,256,256]  f32
    const float* bias = (const float*)d_in[2];   // [256]          f32
    float* out = (float*)d_out;

    static int smem_set = 0;
    if (!smem_set) {
        cudaFuncSetAttribute(conv_mma_kernel,
                             cudaFuncAttributeMaxDynamicSharedMemorySize, 2*STAGE_BYTES);
        smem_set = 1;
    }

    prep_a_kernel<<<NPIX_PAD/2, 128>>>(in);
    prep_b_kernel<<<9*256, 256>>>(wt);
    dim3 grid(2, MTOT/128);   // (2, 784)
    conv_mma_kernel<<<grid, 256, 2*STAGE_BYTES>>>(bias, out);
}

// round 11
// speedup vs baseline: 3.2888x; 1.0252x over previous
#include <cuda_runtime.h>
#include <cuda_fp16.h>
#include <cstdint>

#define BATCH 32
#define HDIM  56
#define WDIM  56
#define CIN   256
#define COUT  256
#define HP    58
#define WP    58
#define MTOT  (BATCH*HDIM*WDIM)        // 100352
#define NPIX_PAD (BATCH*HP*WP)         // 107648
#define NCHUNK 36                      // 9 taps * 4 chunks of 64 channels
#define NSTAGE 3

#define STAGE_BYTES 32768              // A 16KB | B 16KB

// padded activations, fp16: [pix][4 chunks][64ch * 2B] = 512B/pixel
__device__ __align__(1024) unsigned char g_apad[(size_t)NPIX_PAD * 512];
// packed weights fp16: [tap 9][chunk 4][co 256][64ch * 2B = 128B]
__device__ __align__(1024) unsigned char g_bpack[9*4*256*128];

// ---------------- prep kernels ----------------
// 2 pixels per 128-thread block; 64 threads x 4 channels = 256 channels each.
__global__ void prep_a_kernel(const float* __restrict__ in) {
    const int t   = threadIdx.x;
    const int pix = blockIdx.x * 2 + (t >> 6);
    const int tt  = t & 63;
    const int b   = pix / (HP*WP);
    const int rr  = pix % (HP*WP);
    const int yp  = rr / WP, xp = rr % WP;
    const int c0  = tt * 4;               // 0..252
    const int chunk = c0 >> 6, i = c0 & 63;
    unsigned long long hw = 0ull;
    if (!(yp == 0 || yp == HP-1 || xp == 0 || xp == WP-1)) {
        const float4 v = *(const float4*)(in +
            ((size_t)((b*HDIM + (yp-1))*WDIM + (xp-1)))*CIN + c0);
        const float vv[4] = {v.x, v.y, v.z, v.w};
        #pragma unroll
        for (int j = 0; j < 4; j++) {
            __half h = __float2half_rn(vv[j]);
            hw |= (unsigned long long)(*(unsigned short*)&h) << (16*j);
        }
    }
    *(unsigned long long*)(g_apad + (size_t)pix*512 + chunk*128 + i*2) = hw;
}

__global__ void prep_b_kernel(const float* __restrict__ wt) {
    const int k  = blockIdx.x;       // 0..2303 : (ky*3+kx)*256 + ci
    const int co = threadIdx.x;      // 0..255
    const float v = wt[(size_t)k*COUT + co];
    __half h = __float2half_rn(v);
    const int tap = k >> 8, ci = k & 255;
    const int chunk = ci >> 6, i = ci & 63;
    *(unsigned short*)(g_bpack + ((size_t)((tap*4 + chunk)*256 + co))*128 + i*2)
        = *(unsigned short*)&h;
}

// ---------------- device helpers ----------------
__device__ __forceinline__ uint32_t smem_u32(const void* p) {
    uint32_t a;
    asm("{ .reg .u64 t; cvta.to.shared.u64 t, %1; cvt.u32.u64 %0, t; }" : "=r"(a) : "l"(p));
    return a;
}

#define LDSM4(r0,r1,r2,r3,addr) \
    asm volatile("ldmatrix.sync.aligned.m8n8.x4.shared.b16 {%0,%1,%2,%3}, [%4];" \
        : "=r"(r0), "=r"(r1), "=r"(r2), "=r"(r3) : "r"(addr))

__device__ __forceinline__ void mma16816(float* c, const uint32_t* a, const uint32_t* b) {
    asm volatile(
        "mma.sync.aligned.m16n8k16.row.col.f32.f16.f16.f32 "
        "{%0,%1,%2,%3}, {%4,%5,%6,%7}, {%8,%9}, {%0,%1,%2,%3};"
        : "+f"(c[0]), "+f"(c[1]), "+f"(c[2]), "+f"(c[3])
        : "r"(a[0]), "r"(a[1]), "r"(a[2]), "r"(a[3]), "r"(b[0]), "r"(b[1]));
}

// ---------------- main conv kernel ----------------
__global__ void __launch_bounds__(256, 2) conv_mma_kernel(
    const float* __restrict__ bias, float* __restrict__ out)
{
    extern __shared__ unsigned char smem[];
    const uint32_t sb = smem_u32(smem);
    const int t = threadIdx.x;
    const int lane = t & 31, warp = t >> 5;
    const int bm = blockIdx.y * 128;
    const int bn = blockIdx.x * 128;
    const int m0 = (warp >> 2) * 64;     // 2 m-warps
    const int n0 = (warp & 3) * 32;      // 4 n-warps

    // ---- loader setup: t<128 -> A row t; t>=128 -> B row t-128 ----
    const unsigned char* gA = nullptr;
    const unsigned char* gB = nullptr;
    if (t < 128) {
        const int m  = bm + t;
        const int b  = m / (HDIM*WDIM);
        const int r2 = m % (HDIM*WDIM);
        const int y  = r2 / WDIM, x = r2 % WDIM;
        gA = g_apad + (size_t)((b*HP + y)*WP + x) * 512;
    } else {
        gB = g_bpack + ((size_t)(bn + (t - 128))) * 128;
    }
    const int lrow = t & 127;
    const uint32_t swz = (uint32_t)((lrow & 7) << 4);
    const uint32_t sdst_row = (t < 128) ? (uint32_t)(lrow * 128)
                                        : (uint32_t)(16384 + lrow * 128);

    auto load_chunk = [&](int c, int stg) {
        const unsigned char* src;
        if (t < 128) {
            const int tap = c >> 2;
            src = gA + (size_t)((tap/3)*WP + (tap%3))*512 + (c & 3)*128;
        } else {
            src = gB + (size_t)c * (256*128);
        }
        const uint32_t dst = sb + stg*STAGE_BYTES + sdst_row;
        #pragma unroll
        for (int j = 0; j < 8; j++) {
            const uint32_t o = ((uint32_t)(j*16)) ^ swz;
            asm volatile("cp.async.cg.shared.global [%0], [%1], 16;"
                         :: "r"(dst + o), "l"(src + j*16) : "memory");
        }
        asm volatile("cp.async.commit_group;" ::: "memory");
    };

    // ---- ldmatrix lane addressing ----
    const uint32_t lr   = (uint32_t)(lane & 15);
    const uint32_t koff = (uint32_t)((lane >> 4) << 4);
    const uint32_t xorv = (uint32_t)((lane & 7) << 4);

    float acc[4][4][4];
    #pragma unroll
    for (int i = 0; i < 4; i++)
        #pragma unroll
        for (int j = 0; j < 4; j++)
            #pragma unroll
            for (int k = 0; k < 4; k++) acc[i][j][k] = 0.f;

    // prologue: 2 chunks in flight
    load_chunk(0, 0);
    load_chunk(1, 1);

    int stg = 0;        // stage of chunk c
    #pragma unroll 1
    for (int c = 0; c < NCHUNK; c++) {
        // chunk c's group must be complete; chunk c+1's may remain in flight
        if (c == NCHUNK - 1)
            asm volatile("cp.async.wait_group 0;" ::: "memory");
        else
            asm volatile("cp.async.wait_group 1;" ::: "memory");
        __syncthreads();   // single barrier per chunk: also releases stage (c+2)%3,
                           // whose readers (chunk c-1) finished before this point.

        const uint32_t Ab = sb + stg*STAGE_BYTES;
        const uint32_t Bb = Ab + 16384;

        #pragma unroll
        for (int kh = 0; kh < 4; kh++) {
            uint32_t ah[4][4], bh[4][2];
            const uint32_t chi = (uint32_t)(kh*32) + koff;
            #pragma unroll
            for (int mi = 0; mi < 4; mi++) {
                const uint32_t r = Ab + (uint32_t)(m0 + mi*16 + lr)*128;
                LDSM4(ah[mi][0], ah[mi][1], ah[mi][2], ah[mi][3], r + (chi ^ xorv));
            }
            #pragma unroll
            for (int nb = 0; nb < 2; nb++) {
                const uint32_t r = Bb + (uint32_t)(n0 + nb*16 + lr)*128;
                uint32_t b0, b1, b2, b3;
                LDSM4(b0, b1, b2, b3, r + (chi ^ xorv));
                bh[nb*2][0] = b0; bh[nb*2][1] = b2;
                bh[nb*2+1][0] = b1; bh[nb*2+1][1] = b3;
            }
            #pragma unroll
            for (int mi = 0; mi < 4; mi++)
                #pragma unroll
                for (int ni = 0; ni < 4; ni++)
                    mma16816(acc[mi][ni], ah[mi], bh[ni]);

            // issue next-next chunk's loads after kh=0 compute is in flight,
            // so the LSU burst overlaps tensor-pipe drain instead of the
            // first ldmatrix of this chunk.
            if (kh == 0 && c + 2 < NCHUNK) {
                int ns = stg + 2; if (ns >= NSTAGE) ns -= NSTAGE;
                load_chunk(c + 2, ns);
            }
        }

        if (++stg == NSTAGE) stg = 0;
    }

    // ---- epilogue ----
    const int g = lane >> 2, q = lane & 3;
    #pragma unroll
    for (int ni = 0; ni < 4; ni++) {
        const int ncol = bn + n0 + ni*8 + q*2;
        const float2 bv = *(const float2*)(bias + ncol);
        #pragma unroll
        for (int mi = 0; mi < 4; mi++) {
            const int mrow = bm + m0 + mi*16 + g;
            float2 o0, o1;
            o0.x = acc[mi][ni][0] + bv.x; o0.y = acc[mi][ni][1] + bv.y;
            o1.x = acc[mi][ni][2] + bv.x; o1.y = acc[mi][ni][3] + bv.y;
            *(float2*)(out + (size_t)mrow*COUT + ncol)       = o0;
            *(float2*)(out + (size_t)(mrow+8)*COUT + ncol)   = o1;
        }
    }
}

// ---------------- launch ----------------
extern "C" void kernel_launch(void* const* d_in, const int* in_sizes, int n_in,
                              void* d_out, int out_size) {
    const float* in   = (const float*)d_in[0];   // [32,56,56,256] f32
    const float* wt   = (const float*)d_in[1];   // [3,3,256,256]  f32
    const float* bias = (const float*)d_in[2];   // [256]          f32
    float* out = (float*)d_out;

    static int smem_set = 0;
    if (!smem_set) {
        cudaFuncSetAttribute(conv_mma_kernel,
                             cudaFuncAttributeMaxDynamicSharedMemorySize, NSTAGE*STAGE_BYTES);
        smem_set = 1;
    }

    prep_a_kernel<<<NPIX_PAD/2, 128>>>(in);
    prep_b_kernel<<<9*256, 256>>>(wt);
    dim3 grid(2, MTOT/128);   // (2, 784)
    conv_mma_kernel<<<grid, 256, NSTAGE*STAGE_BYTES>>>(bias, out);
}